// round 1
// baseline (speedup 1.0000x reference)
#include <cuda_runtime.h>
#include <cuda_bf16.h>
#include <cstdint>

// Problem constants
#define Bsz   4
#define Ssz   2048
#define HID   2048
#define HEADS 16
#define HDIM  128
#define MBsz  16
#define NCH   128          // Ssz / MBsz
#define Mrows (Bsz*Ssz)    // 8192

// Scratch (device globals: allocation-free rule)
__device__ float g_k[(size_t)Mrows * HID];
__device__ float g_v[(size_t)Mrows * HID];
__device__ float g_o[(size_t)Mrows * HID];

// ---------------------------------------------------------------------------
// packed f32x2 helpers (FFMA2 path, sm_100+)
// ---------------------------------------------------------------------------
__device__ __forceinline__ unsigned long long pack_dup(float x) {
    unsigned long long r;
    unsigned u = __float_as_uint(x);
    asm("mov.b64 %0, {%1, %1};" : "=l"(r) : "r"(u));
    return r;
}
__device__ __forceinline__ void ffma2(unsigned long long& d,
                                      unsigned long long a,
                                      unsigned long long b) {
    asm("fma.rn.f32x2 %0, %1, %2, %0;" : "+l"(d) : "l"(a), "l"(b));
}
__device__ __forceinline__ float2 unpack2(unsigned long long v) {
    float2 f;
    f.x = __uint_as_float((unsigned)(v & 0xffffffffull));
    f.y = __uint_as_float((unsigned)(v >> 32));
    return f;
}

// ---------------------------------------------------------------------------
// SGEMM:  C[M,N] = A[M,K] @ B[N,K]^T  (+ optional residual Res[M,N])
// BM=BN=128, BK=8, 256 threads, 8x8 per-thread tile, f32x2 accumulators
// ---------------------------------------------------------------------------
#define BM 128
#define BN 128
#define BK 8

__global__ __launch_bounds__(256, 2)
void sgemm_nt_kernel(const float* __restrict__ A,
                     const float* __restrict__ B,
                     float*       __restrict__ C,
                     const float* __restrict__ Res,
                     int M, int N, int K)
{
    __shared__ __align__(16) float As[BK][BM];
    __shared__ __align__(16) float Bs[BK][BN];

    const int tid  = threadIdx.x;
    const int row0 = blockIdx.y * BM;
    const int col0 = blockIdx.x * BN;

    const int lr = tid >> 1;          // 0..127 : row within tile
    const int lc = (tid & 1) * 4;     // 0 or 4 : k within tile

    const int ty = tid >> 4;          // 0..15 m-group
    const int tx = tid & 15;          // 0..15 n-group

    const float* Aptr = A + (size_t)(row0 + lr) * K + lc;
    const float* Bptr = B + (size_t)(col0 + lr) * K + lc;

    unsigned long long acc[8][4];
#pragma unroll
    for (int i = 0; i < 8; ++i)
#pragma unroll
        for (int j = 0; j < 4; ++j) acc[i][j] = 0ull;

    for (int kt = 0; kt < K; kt += BK) {
        float4 av = *(const float4*)(Aptr + kt);
        float4 bv = *(const float4*)(Bptr + kt);
        __syncthreads();   // previous-iter readers done
        As[lc + 0][lr] = av.x; As[lc + 1][lr] = av.y;
        As[lc + 2][lr] = av.z; As[lc + 3][lr] = av.w;
        Bs[lc + 0][lr] = bv.x; Bs[lc + 1][lr] = bv.y;
        Bs[lc + 2][lr] = bv.z; Bs[lc + 3][lr] = bv.w;
        __syncthreads();

#pragma unroll
        for (int kk = 0; kk < BK; ++kk) {
            float4 a0 = *(const float4*)&As[kk][ty * 8];
            float4 a1 = *(const float4*)&As[kk][ty * 8 + 4];
            ulonglong2 b01 = *(const ulonglong2*)&Bs[kk][tx * 8];
            ulonglong2 b23 = *(const ulonglong2*)&Bs[kk][tx * 8 + 4];
            float am[8] = {a0.x, a0.y, a0.z, a0.w, a1.x, a1.y, a1.z, a1.w};
#pragma unroll
            for (int i = 0; i < 8; ++i) {
                unsigned long long aa = pack_dup(am[i]);
                ffma2(acc[i][0], aa, b01.x);
                ffma2(acc[i][1], aa, b01.y);
                ffma2(acc[i][2], aa, b23.x);
                ffma2(acc[i][3], aa, b23.y);
            }
        }
    }

    // epilogue
#pragma unroll
    for (int i = 0; i < 8; ++i) {
        const int r = row0 + ty * 8 + i;
        float out[8];
#pragma unroll
        for (int j = 0; j < 4; ++j) {
            float2 f = unpack2(acc[i][j]);
            out[2 * j]     = f.x;
            out[2 * j + 1] = f.y;
        }
        const size_t base = (size_t)r * N + col0 + tx * 8;
        if (Res) {
            float4 r0 = *(const float4*)(Res + base);
            float4 r1 = *(const float4*)(Res + base + 4);
            out[0] += r0.x; out[1] += r0.y; out[2] += r0.z; out[3] += r0.w;
            out[4] += r1.x; out[5] += r1.y; out[6] += r1.z; out[7] += r1.w;
        }
        *(float4*)(C + base)     = make_float4(out[0], out[1], out[2], out[3]);
        *(float4*)(C + base + 4) = make_float4(out[4], out[5], out[6], out[7]);
    }
}

// ---------------------------------------------------------------------------
// RoPE on g_k, layout [B*S, HID]; head h occupies cols h*128..h*128+127
// ---------------------------------------------------------------------------
__global__ void rope_kernel(float* __restrict__ k)
{
    const int gid = blockIdx.x * blockDim.x + threadIdx.x;
    const int total = Bsz * Ssz * HEADS * (HDIM / 2);
    if (gid >= total) return;
    const int i   = gid & 63;            // pair index within head
    const int h   = (gid >> 6) & (HEADS - 1);
    const int row = gid >> 10;           // b*S + s
    const int s   = row & (Ssz - 1);

    // inv_freq = 10000^{-i/64}  (via exp2)
    const float c = 0.20762050593046013f;   // log2(10000)/64
    const float inv = exp2f(-c * (float)i);
    const float ang = (float)s * inv;
    float sn, cs;
    __sincosf(ang, &sn, &cs);
    // use precise sin/cos (not fast-math intrinsic) for accuracy:
    sn = sinf(ang); cs = cosf(ang);

    float* p = k + (size_t)row * HID + h * HDIM;
    const float k1 = p[i];
    const float k2 = p[i + 64];
    p[i]      = k1 * cs - k2 * sn;
    p[i + 64] = k2 * cs + k1 * sn;
}

// ---------------------------------------------------------------------------
// TTT scan: one CTA per (b,h). W [128x128] resident in smem (stride 132).
// Per chunk: pred=KW, err=pred-V, W -= c*K^T err, out=K W_new.
// 512 threads.
// ---------------------------------------------------------------------------
#define WLD 132
#define SCAN_SMEM ((128 * WLD + 2048 + 2048) * 4)

__global__ __launch_bounds__(512, 1)
void ttt_scan_kernel(const float* __restrict__ gk,
                     const float* __restrict__ gv,
                     const float* __restrict__ W0,
                     float*       __restrict__ go)
{
    extern __shared__ float sm[];
    float* Ws = sm;                     // 128 * 132
    float* Ks = sm + 128 * WLD;         // 16 * 128
    float* Es = Ks + 2048;              // 16 * 128

    const int bh = blockIdx.x;
    const int b  = bh >> 4;
    const int h  = bh & 15;
    const int t  = threadIdx.x;

    // load W0
    const float* W0p = W0 + (size_t)bh * HDIM * HDIM;
    for (int i = t; i < HDIM * HDIM; i += 512) {
        int d = i >> 7, e = i & 127;
        Ws[d * WLD + e] = W0p[i];
    }

    const float* kbase = gk + (size_t)b * Ssz * HID + h * HDIM;
    const float* vbase = gv + (size_t)b * Ssz * HID + h * HDIM;
    float*       obase = go + (size_t)b * Ssz * HID + h * HDIM;

    // thread maps
    const int m3 = t >> 5;              // 0..15 (pred/out row)
    const int e3 = (t & 31) * 4;        // col group of 4
    const int d0 = (t >> 4) * 4;        // 0..124 (grad d tile)
    const int e5 = (t & 15) * 8;        // grad e tile
    const float cgrad = 2.0f / (MBsz * HDIM);

    for (int c = 0; c < NCH; ++c) {
        __syncthreads();   // Ks/Es free from previous iter readers
        // load K,V chunk (16 x 128)
        for (int i = t; i < MBsz * HDIM; i += 512) {
            int m = i >> 7, d = i & 127;
            size_t off = (size_t)((c << 4) + m) * HID + d;
            Ks[i] = kbase[off];
            Es[i] = vbase[off];
        }
        __syncthreads();

        // ---- pred & err (each thread: 4 outputs, row m3, cols e3..e3+3)
        {
            float ap0 = 0.f, ap1 = 0.f, ap2 = 0.f, ap3 = 0.f;
            const float* krow = &Ks[m3 << 7];
#pragma unroll 8
            for (int d = 0; d < HDIM; d += 4) {
                float4 kq = *(const float4*)&krow[d];
                float4 w0 = *(const float4*)&Ws[(d + 0) * WLD + e3];
                float4 w1 = *(const float4*)&Ws[(d + 1) * WLD + e3];
                float4 w2 = *(const float4*)&Ws[(d + 2) * WLD + e3];
                float4 w3 = *(const float4*)&Ws[(d + 3) * WLD + e3];
                ap0 += kq.x * w0.x; ap1 += kq.x * w0.y; ap2 += kq.x * w0.z; ap3 += kq.x * w0.w;
                ap0 += kq.y * w1.x; ap1 += kq.y * w1.y; ap2 += kq.y * w1.z; ap3 += kq.y * w1.w;
                ap0 += kq.z * w2.x; ap1 += kq.z * w2.y; ap2 += kq.z * w2.z; ap3 += kq.z * w2.w;
                ap0 += kq.w * w3.x; ap1 += kq.w * w3.y; ap2 += kq.w * w3.z; ap3 += kq.w * w3.w;
            }
            float4 vv = *(const float4*)&Es[(m3 << 7) + e3];
            float4 er = make_float4(ap0 - vv.x, ap1 - vv.y, ap2 - vv.z, ap3 - vv.w);
            *(float4*)&Es[(m3 << 7) + e3] = er;   // same element read/written by this thread
        }
        __syncthreads();

        // ---- W update: grad[d][e] = sum_m K[m][d] * E[m][e]; W -= c*grad
        {
            float ag[4][8];
#pragma unroll
            for (int i = 0; i < 4; ++i)
#pragma unroll
                for (int j = 0; j < 8; ++j) ag[i][j] = 0.f;

#pragma unroll 4
            for (int mm = 0; mm < MBsz; ++mm) {
                float4 kv  = *(const float4*)&Ks[(mm << 7) + d0];
                float4 ea  = *(const float4*)&Es[(mm << 7) + e5];
                float4 eb  = *(const float4*)&Es[(mm << 7) + e5 + 4];
                float ev[8] = {ea.x, ea.y, ea.z, ea.w, eb.x, eb.y, eb.z, eb.w};
                float kw[4] = {kv.x, kv.y, kv.z, kv.w};
#pragma unroll
                for (int i = 0; i < 4; ++i)
#pragma unroll
                    for (int j = 0; j < 8; ++j) ag[i][j] += kw[i] * ev[j];
            }
#pragma unroll
            for (int i = 0; i < 4; ++i) {
                float* wr = &Ws[(d0 + i) * WLD + e5];
                float4 w0 = *(float4*)wr;
                float4 w1 = *(float4*)(wr + 4);
                w0.x -= cgrad * ag[i][0]; w0.y -= cgrad * ag[i][1];
                w0.z -= cgrad * ag[i][2]; w0.w -= cgrad * ag[i][3];
                w1.x -= cgrad * ag[i][4]; w1.y -= cgrad * ag[i][5];
                w1.z -= cgrad * ag[i][6]; w1.w -= cgrad * ag[i][7];
                *(float4*)wr       = w0;
                *(float4*)(wr + 4) = w1;
            }
        }
        __syncthreads();

        // ---- out = K @ W_new, write to global
        {
            float ap0 = 0.f, ap1 = 0.f, ap2 = 0.f, ap3 = 0.f;
            const float* krow = &Ks[m3 << 7];
#pragma unroll 8
            for (int d = 0; d < HDIM; d += 4) {
                float4 kq = *(const float4*)&krow[d];
                float4 w0 = *(const float4*)&Ws[(d + 0) * WLD + e3];
                float4 w1 = *(const float4*)&Ws[(d + 1) * WLD + e3];
                float4 w2 = *(const float4*)&Ws[(d + 2) * WLD + e3];
                float4 w3 = *(const float4*)&Ws[(d + 3) * WLD + e3];
                ap0 += kq.x * w0.x; ap1 += kq.x * w0.y; ap2 += kq.x * w0.z; ap3 += kq.x * w0.w;
                ap0 += kq.y * w1.x; ap1 += kq.y * w1.y; ap2 += kq.y * w1.z; ap3 += kq.y * w1.w;
                ap0 += kq.z * w2.x; ap1 += kq.z * w2.y; ap2 += kq.z * w2.z; ap3 += kq.z * w2.w;
                ap0 += kq.w * w3.x; ap1 += kq.w * w3.y; ap2 += kq.w * w3.z; ap3 += kq.w * w3.w;
            }
            size_t orow = (size_t)((c << 4) + m3) * HID + e3;
            *(float4*)&obase[orow] = make_float4(ap0, ap1, ap2, ap3);
        }
    }
}

// ---------------------------------------------------------------------------
// LayerNorm (in place on g_o), 1 block per row of 2048
// ---------------------------------------------------------------------------
__global__ __launch_bounds__(256)
void ln_kernel(float* __restrict__ o,
               const float* __restrict__ g,
               const float* __restrict__ beta)
{
    __shared__ float s1[8], s2[8];
    const int row = blockIdx.x;
    const int t   = threadIdx.x;
    float* p = o + (size_t)row * HID;

    float4 v0 = *(const float4*)(p + t * 8);
    float4 v1 = *(const float4*)(p + t * 8 + 4);
    float s  = v0.x + v0.y + v0.z + v0.w + v1.x + v1.y + v1.z + v1.w;
    float ss = v0.x*v0.x + v0.y*v0.y + v0.z*v0.z + v0.w*v0.w
             + v1.x*v1.x + v1.y*v1.y + v1.z*v1.z + v1.w*v1.w;
#pragma unroll
    for (int off = 16; off > 0; off >>= 1) {
        s  += __shfl_xor_sync(0xffffffffu, s,  off);
        ss += __shfl_xor_sync(0xffffffffu, ss, off);
    }
    const int w = t >> 5;
    if ((t & 31) == 0) { s1[w] = s; s2[w] = ss; }
    __syncthreads();
    float tot = 0.f, tot2 = 0.f;
#pragma unroll
    for (int i = 0; i < 8; ++i) { tot += s1[i]; tot2 += s2[i]; }
    const float mu  = tot * (1.0f / HID);
    const float var = tot2 * (1.0f / HID) - mu * mu;
    const float inv = rsqrtf(var + 1e-5f);

    float4 g0 = *(const float4*)(g + t * 8);
    float4 g1 = *(const float4*)(g + t * 8 + 4);
    float4 b0 = *(const float4*)(beta + t * 8);
    float4 b1 = *(const float4*)(beta + t * 8 + 4);
    v0.x = (v0.x - mu) * inv * g0.x + b0.x;
    v0.y = (v0.y - mu) * inv * g0.y + b0.y;
    v0.z = (v0.z - mu) * inv * g0.z + b0.z;
    v0.w = (v0.w - mu) * inv * g0.w + b0.w;
    v1.x = (v1.x - mu) * inv * g1.x + b1.x;
    v1.y = (v1.y - mu) * inv * g1.y + b1.y;
    v1.z = (v1.z - mu) * inv * g1.z + b1.z;
    v1.w = (v1.w - mu) * inv * g1.w + b1.w;
    *(float4*)(p + t * 8)     = v0;
    *(float4*)(p + t * 8 + 4) = v1;
}

// ---------------------------------------------------------------------------
// launch
// ---------------------------------------------------------------------------
extern "C" void kernel_launch(void* const* d_in, const int* in_sizes, int n_in,
                              void* d_out, int out_size)
{
    const float* x   = (const float*)d_in[0];
    const float* Wk  = (const float*)d_in[1];
    const float* Wv  = (const float*)d_in[2];
    const float* Wo  = (const float*)d_in[3];
    const float* lng = (const float*)d_in[4];
    const float* lnb = (const float*)d_in[5];
    const float* W0  = (const float*)d_in[6];
    float* out = (float*)d_out;

    float *gk, *gv, *go;
    cudaGetSymbolAddress((void**)&gk, g_k);
    cudaGetSymbolAddress((void**)&gv, g_v);
    cudaGetSymbolAddress((void**)&go, g_o);

    cudaFuncSetAttribute(ttt_scan_kernel,
                         cudaFuncAttributeMaxDynamicSharedMemorySize, SCAN_SMEM);

    dim3 gg(HID / BN, Mrows / BM);     // (16, 64)
    dim3 bb(256);

    // k = x @ Wk^T ; v = x @ Wv^T
    sgemm_nt_kernel<<<gg, bb>>>(x, Wk, gk, nullptr, Mrows, HID, HID);
    sgemm_nt_kernel<<<gg, bb>>>(x, Wv, gv, nullptr, Mrows, HID, HID);

    // RoPE on k
    {
        const int total = Bsz * Ssz * HEADS * (HDIM / 2);
        rope_kernel<<<(total + 255) / 256, 256>>>(gk);
    }

    // TTT scan -> o
    ttt_scan_kernel<<<Bsz * HEADS, 512, SCAN_SMEM>>>(gk, gv, W0, go);

    // LayerNorm in place
    ln_kernel<<<Mrows, 256>>>(go, lng, lnb);

    // out = x + o_ln @ Wo^T
    sgemm_nt_kernel<<<gg, bb>>>(go, Wo, out, x, Mrows, HID, HID);
}

// round 3
// speedup vs baseline: 2.0169x; 2.0169x over previous
#include <cuda_runtime.h>
#include <cuda_bf16.h>
#include <cstdint>

// Problem constants
#define Bsz   4
#define Ssz   2048
#define HID   2048
#define HEADS 16
#define HDIM  128
#define MBsz  16
#define NCH   128
#define Mrows (Bsz*Ssz)    // 8192
#define Kdim  2048
#define Ndim  2048

// Scratch (device globals: allocation-free rule)
__device__ float g_k[(size_t)Mrows * HID];
__device__ float g_v[(size_t)Mrows * HID];
__device__ float g_o[(size_t)Mrows * HID];
__device__ __nv_bfloat16 g_ahi[(size_t)Mrows * HID];
__device__ __nv_bfloat16 g_alo[(size_t)Mrows * HID];
__device__ __nv_bfloat16 g_whi[(size_t)HID * HID];
__device__ __nv_bfloat16 g_wlo[(size_t)HID * HID];

// ---------------------------------------------------------------------------
// helpers (baseline PTX only: cp.async / ldmatrix / mma.sync — sm_80 features)
// ---------------------------------------------------------------------------
__device__ __forceinline__ uint32_t smem_u32(const void* p) {
    uint32_t a;
    asm("{ .reg .u64 t; cvta.to.shared.u64 t, %1; cvt.u32.u64 %0, t; }"
        : "=r"(a) : "l"(p));
    return a;
}

#define SWZ(x) ((x) ^ (((x) >> 3) & 0x70))

__device__ __forceinline__ void cp16(uint32_t dst, const void* src) {
    asm volatile("cp.async.cg.shared.global [%0], [%1], 16;\n"
                 :: "r"(dst), "l"(src) : "memory");
}
__device__ __forceinline__ void cp_commit() {
    asm volatile("cp.async.commit_group;\n" ::: "memory");
}
template <int N> __device__ __forceinline__ void cp_wait() {
    asm volatile("cp.async.wait_group %0;\n" :: "n"(N) : "memory");
}

__device__ __forceinline__ void ldsm4(uint32_t r[4], uint32_t a) {
    asm volatile("ldmatrix.sync.aligned.m8n8.x4.shared.b16 {%0,%1,%2,%3}, [%4];"
                 : "=r"(r[0]), "=r"(r[1]), "=r"(r[2]), "=r"(r[3]) : "r"(a));
}

__device__ __forceinline__ void mma16816(float c[4], const uint32_t a[4],
                                         const uint32_t b0, const uint32_t b1) {
    asm volatile(
        "mma.sync.aligned.m16n8k16.row.col.f32.bf16.bf16.f32 "
        "{%0,%1,%2,%3}, {%4,%5,%6,%7}, {%8,%9}, {%0,%1,%2,%3};"
        : "+f"(c[0]), "+f"(c[1]), "+f"(c[2]), "+f"(c[3])
        : "r"(a[0]), "r"(a[1]), "r"(a[2]), "r"(a[3]), "r"(b0), "r"(b1));
}

// ---------------------------------------------------------------------------
// fp32 -> bf16 hi/lo split converter
// ---------------------------------------------------------------------------
__global__ __launch_bounds__(256)
void cvt_hilo_kernel(const float* __restrict__ s,
                     __nv_bfloat16* __restrict__ hi,
                     __nv_bfloat16* __restrict__ lo, int n4)
{
    int i = blockIdx.x * blockDim.x + threadIdx.x;
    if (i >= n4) return;
    float4 v = ((const float4*)s)[i];
    __nv_bfloat16 h0 = __float2bfloat16_rn(v.x);
    __nv_bfloat16 h1 = __float2bfloat16_rn(v.y);
    __nv_bfloat16 h2 = __float2bfloat16_rn(v.z);
    __nv_bfloat16 h3 = __float2bfloat16_rn(v.w);
    __nv_bfloat16 l0 = __float2bfloat16_rn(v.x - __bfloat162float(h0));
    __nv_bfloat16 l1 = __float2bfloat16_rn(v.y - __bfloat162float(h1));
    __nv_bfloat16 l2 = __float2bfloat16_rn(v.z - __bfloat162float(h2));
    __nv_bfloat16 l3 = __float2bfloat16_rn(v.w - __bfloat162float(h3));
    __nv_bfloat162* H = (__nv_bfloat162*)hi;
    __nv_bfloat162* L = (__nv_bfloat162*)lo;
    H[2 * i]     = __halves2bfloat162(h0, h1);
    H[2 * i + 1] = __halves2bfloat162(h2, h3);
    L[2 * i]     = __halves2bfloat162(l0, l1);
    L[2 * i + 1] = __halves2bfloat162(l2, l3);
}

// ---------------------------------------------------------------------------
// mma.sync bf16 hi/lo GEMM: C[M,N] = A[M,K] @ B[N,K]^T (+ optional residual)
// CTA tile 128x128, BK=64, SW128 smem, 3-stage cp.async pipeline.
// 8 warps, warp tile 64(m) x 32(n). 3 products: AhBh + AhBl + AlBh.
// ---------------------------------------------------------------------------
#define GS      3
#define TILE_B  16384            // 128 rows x 128B
#define STAGE_B (4 * TILE_B)     // Ahi, Alo, Bhi, Blo = 64KB
#define GEMM_SMEM (1024 + GS * STAGE_B)
#define KTILES  (Kdim / 64)      // 32

__global__ __launch_bounds__(256, 1)
void gemm_mma_kernel(const __nv_bfloat16* __restrict__ Ahi,
                     const __nv_bfloat16* __restrict__ Alo,
                     const __nv_bfloat16* __restrict__ Bhi,
                     const __nv_bfloat16* __restrict__ Blo,
                     float* __restrict__ C,
                     const float* __restrict__ Res)
{
    extern __shared__ uint8_t smraw[];
    const uint32_t s0 = (smem_u32(smraw) + 1023u) & ~1023u;

    const int tid  = threadIdx.x;
    const int wid  = tid >> 5;
    const int lane = tid & 31;
    const int wm   = wid & 1;        // 2 m-warps  (64 rows each)
    const int wn   = wid >> 1;       // 4 n-warps  (32 cols each)
    const int m0 = blockIdx.y * 128;
    const int n0 = blockIdx.x * 128;

    // ---- per-lane ldmatrix address bases (byte offsets into a tile) ----
    // A (m16 tiles): mat = lane/8 ; bit0 -> +8 rows, bit1 -> +16B (k+8)
    uint32_t aBase[4];
    {
        int amat = lane >> 3, al = lane & 7;
        int rofs = ((amat & 1) << 3) + al;
        uint32_t akb = (uint32_t)((amat >> 1) << 4);
#pragma unroll
        for (int mf = 0; mf < 4; ++mf) {
            uint32_t r = (uint32_t)(wm * 64 + mf * 16 + rofs) * 128u;
            aBase[mf] = SWZ(r) ^ akb;
        }
    }
    // B (two n8 tiles per ldsm4): mat bit1 -> +8 rows(n), bit0 -> +16B (k+8)
    uint32_t bBase[2];
    {
        int bmat = lane >> 3, bl = lane & 7;
        int rofs = ((bmat >> 1) << 3) + bl;
        uint32_t bkb = (uint32_t)((bmat & 1) << 4);
#pragma unroll
        for (int nfp = 0; nfp < 2; ++nfp) {
            uint32_t r = (uint32_t)(wn * 32 + nfp * 16 + rofs) * 128u;
            bBase[nfp] = SWZ(r) ^ bkb;
        }
    }

    // ---- stage loader: 4 tiles x 128 rows x 8 chunks of 16B ----
    auto load_stage = [&](int kt) {
        uint32_t sb = s0 + (uint32_t)(kt % GS) * STAGE_B;
        const size_t kof = (size_t)kt * 64;
#pragma unroll
        for (int j = 0; j < 4; ++j) {
            int q = j * 256 + tid;
            int row = q >> 3, ch = q & 7;
            uint32_t so = SWZ((uint32_t)(row * 128 + ch * 16));
            size_t ga = (size_t)(m0 + row) * Kdim + kof + (size_t)ch * 8;
            size_t gb = (size_t)(n0 + row) * Kdim + kof + (size_t)ch * 8;
            cp16(sb + so,              Ahi + ga);
            cp16(sb + TILE_B + so,     Alo + ga);
            cp16(sb + 2 * TILE_B + so, Bhi + gb);
            cp16(sb + 3 * TILE_B + so, Blo + gb);
        }
        cp_commit();
    };

    float acc[4][4][4];
#pragma unroll
    for (int i = 0; i < 4; ++i)
#pragma unroll
        for (int j = 0; j < 4; ++j)
#pragma unroll
            for (int r = 0; r < 4; ++r) acc[i][j][r] = 0.f;

    load_stage(0);
    load_stage(1);

    for (int it = 0; it < KTILES; ++it) {
        cp_wait<1>();
        __syncthreads();
        if (it + 2 < KTILES) load_stage(it + 2);

        const uint32_t sb = s0 + (uint32_t)(it % GS) * STAGE_B;
#pragma unroll
        for (int kk = 0; kk < 4; ++kk) {
            const uint32_t kx = (uint32_t)(kk * 32);
            uint32_t ah[4][4], al[4][4];
#pragma unroll
            for (int mf = 0; mf < 4; ++mf) {
                ldsm4(ah[mf], sb + (aBase[mf] ^ kx));
                ldsm4(al[mf], sb + TILE_B + (aBase[mf] ^ kx));
            }
            uint32_t bh[4][2], bl[4][2];
#pragma unroll
            for (int nfp = 0; nfp < 2; ++nfp) {
                uint32_t t[4];
                ldsm4(t, sb + 2 * TILE_B + (bBase[nfp] ^ kx));
                bh[2 * nfp][0] = t[0]; bh[2 * nfp][1] = t[1];
                bh[2 * nfp + 1][0] = t[2]; bh[2 * nfp + 1][1] = t[3];
                ldsm4(t, sb + 3 * TILE_B + (bBase[nfp] ^ kx));
                bl[2 * nfp][0] = t[0]; bl[2 * nfp][1] = t[1];
                bl[2 * nfp + 1][0] = t[2]; bl[2 * nfp + 1][1] = t[3];
            }
#pragma unroll
            for (int mf = 0; mf < 4; ++mf)
#pragma unroll
                for (int nf = 0; nf < 4; ++nf) {
                    mma16816(acc[mf][nf], ah[mf], bh[nf][0], bh[nf][1]);
                    mma16816(acc[mf][nf], ah[mf], bl[nf][0], bl[nf][1]);
                    mma16816(acc[mf][nf], al[mf], bh[nf][0], bh[nf][1]);
                }
        }
    }

    // ---- epilogue: direct register -> global (float2 per frag-half) ----
    const int cm = (lane >> 2);
    const int cn = (lane & 3) * 2;
#pragma unroll
    for (int mf = 0; mf < 4; ++mf) {
        const int row = m0 + wm * 64 + mf * 16 + cm;
#pragma unroll
        for (int nf = 0; nf < 4; ++nf) {
            const int col = n0 + wn * 32 + nf * 8 + cn;
            float2 v0 = make_float2(acc[mf][nf][0], acc[mf][nf][1]);
            float2 v1 = make_float2(acc[mf][nf][2], acc[mf][nf][3]);
            if (Res) {
                float2 r0 = *(const float2*)(Res + (size_t)row * Ndim + col);
                float2 r1 = *(const float2*)(Res + (size_t)(row + 8) * Ndim + col);
                v0.x += r0.x; v0.y += r0.y;
                v1.x += r1.x; v1.y += r1.y;
            }
            *(float2*)(C + (size_t)row * Ndim + col)       = v0;
            *(float2*)(C + (size_t)(row + 8) * Ndim + col) = v1;
        }
    }
}

// ---------------------------------------------------------------------------
// RoPE on g_k
// ---------------------------------------------------------------------------
__global__ void rope_kernel(float* __restrict__ k)
{
    const int gid = blockIdx.x * blockDim.x + threadIdx.x;
    const int total = Bsz * Ssz * HEADS * (HDIM / 2);
    if (gid >= total) return;
    const int i   = gid & 63;
    const int h   = (gid >> 6) & (HEADS - 1);
    const int row = gid >> 10;
    const int s   = row & (Ssz - 1);

    const float c = 0.20762050593046013f;   // log2(10000)/64
    const float inv = exp2f(-c * (float)i);
    const float ang = (float)s * inv;
    float sn = sinf(ang), cs = cosf(ang);

    float* p = k + (size_t)row * HID + h * HDIM;
    const float k1 = p[i];
    const float k2 = p[i + 64];
    p[i]      = k1 * cs - k2 * sn;
    p[i + 64] = k2 * cs + k1 * sn;
}

// ---------------------------------------------------------------------------
// TTT scan: one CTA per (b,h). W [128x128] resident in smem (stride 132).
// ---------------------------------------------------------------------------
#define WLD 132
#define SCAN_SMEM ((128 * WLD + 2048 + 2048) * 4)

__global__ __launch_bounds__(512, 1)
void ttt_scan_kernel(const float* __restrict__ gk,
                     const float* __restrict__ gv,
                     const float* __restrict__ W0,
                     float*       __restrict__ go)
{
    extern __shared__ float sm[];
    float* Ws = sm;
    float* Ks = sm + 128 * WLD;
    float* Es = Ks + 2048;

    const int bh = blockIdx.x;
    const int b  = bh >> 4;
    const int h  = bh & 15;
    const int t  = threadIdx.x;

    const float* W0p = W0 + (size_t)bh * HDIM * HDIM;
    for (int i = t; i < HDIM * HDIM; i += 512) {
        int d = i >> 7, e = i & 127;
        Ws[d * WLD + e] = W0p[i];
    }

    const float* kbase = gk + (size_t)b * Ssz * HID + h * HDIM;
    const float* vbase = gv + (size_t)b * Ssz * HID + h * HDIM;
    float*       obase = go + (size_t)b * Ssz * HID + h * HDIM;

    const int m3 = t >> 5;
    const int e3 = (t & 31) * 4;
    const int d0 = (t >> 4) * 4;
    const int e5 = (t & 15) * 8;
    const float cgrad = 2.0f / (MBsz * HDIM);

    for (int c = 0; c < NCH; ++c) {
        __syncthreads();
        for (int i = t; i < MBsz * HDIM; i += 512) {
            int m = i >> 7, d = i & 127;
            size_t off = (size_t)((c << 4) + m) * HID + d;
            Ks[i] = kbase[off];
            Es[i] = vbase[off];
        }
        __syncthreads();

        {
            float ap0 = 0.f, ap1 = 0.f, ap2 = 0.f, ap3 = 0.f;
            const float* krow = &Ks[m3 << 7];
#pragma unroll 8
            for (int d = 0; d < HDIM; d += 4) {
                float4 kq = *(const float4*)&krow[d];
                float4 w0 = *(const float4*)&Ws[(d + 0) * WLD + e3];
                float4 w1 = *(const float4*)&Ws[(d + 1) * WLD + e3];
                float4 w2 = *(const float4*)&Ws[(d + 2) * WLD + e3];
                float4 w3 = *(const float4*)&Ws[(d + 3) * WLD + e3];
                ap0 += kq.x * w0.x; ap1 += kq.x * w0.y; ap2 += kq.x * w0.z; ap3 += kq.x * w0.w;
                ap0 += kq.y * w1.x; ap1 += kq.y * w1.y; ap2 += kq.y * w1.z; ap3 += kq.y * w1.w;
                ap0 += kq.z * w2.x; ap1 += kq.z * w2.y; ap2 += kq.z * w2.z; ap3 += kq.z * w2.w;
                ap0 += kq.w * w3.x; ap1 += kq.w * w3.y; ap2 += kq.w * w3.z; ap3 += kq.w * w3.w;
            }
            float4 vv = *(const float4*)&Es[(m3 << 7) + e3];
            float4 er = make_float4(ap0 - vv.x, ap1 - vv.y, ap2 - vv.z, ap3 - vv.w);
            *(float4*)&Es[(m3 << 7) + e3] = er;
        }
        __syncthreads();

        {
            float ag[4][8];
#pragma unroll
            for (int i = 0; i < 4; ++i)
#pragma unroll
                for (int j = 0; j < 8; ++j) ag[i][j] = 0.f;

#pragma unroll 4
            for (int mm = 0; mm < MBsz; ++mm) {
                float4 kv  = *(const float4*)&Ks[(mm << 7) + d0];
                float4 ea  = *(const float4*)&Es[(mm << 7) + e5];
                float4 eb  = *(const float4*)&Es[(mm << 7) + e5 + 4];
                float ev[8] = {ea.x, ea.y, ea.z, ea.w, eb.x, eb.y, eb.z, eb.w};
                float kw[4] = {kv.x, kv.y, kv.z, kv.w};
#pragma unroll
                for (int i = 0; i < 4; ++i)
#pragma unroll
                    for (int j = 0; j < 8; ++j) ag[i][j] += kw[i] * ev[j];
            }
#pragma unroll
            for (int i = 0; i < 4; ++i) {
                float* wr = &Ws[(d0 + i) * WLD + e5];
                float4 w0 = *(float4*)wr;
                float4 w1 = *(float4*)(wr + 4);
                w0.x -= cgrad * ag[i][0]; w0.y -= cgrad * ag[i][1];
                w0.z -= cgrad * ag[i][2]; w0.w -= cgrad * ag[i][3];
                w1.x -= cgrad * ag[i][4]; w1.y -= cgrad * ag[i][5];
                w1.z -= cgrad * ag[i][6]; w1.w -= cgrad * ag[i][7];
                *(float4*)wr       = w0;
                *(float4*)(wr + 4) = w1;
            }
        }
        __syncthreads();

        {
            float ap0 = 0.f, ap1 = 0.f, ap2 = 0.f, ap3 = 0.f;
            const float* krow = &Ks[m3 << 7];
#pragma unroll 8
            for (int d = 0; d < HDIM; d += 4) {
                float4 kq = *(const float4*)&krow[d];
                float4 w0 = *(const float4*)&Ws[(d + 0) * WLD + e3];
                float4 w1 = *(const float4*)&Ws[(d + 1) * WLD + e3];
                float4 w2 = *(const float4*)&Ws[(d + 2) * WLD + e3];
                float4 w3 = *(const float4*)&Ws[(d + 3) * WLD + e3];
                ap0 += kq.x * w0.x; ap1 += kq.x * w0.y; ap2 += kq.x * w0.z; ap3 += kq.x * w0.w;
                ap0 += kq.y * w1.x; ap1 += kq.y * w1.y; ap2 += kq.y * w1.z; ap3 += kq.y * w1.w;
                ap0 += kq.z * w2.x; ap1 += kq.z * w2.y; ap2 += kq.z * w2.z; ap3 += kq.z * w2.w;
                ap0 += kq.w * w3.x; ap1 += kq.w * w3.y; ap2 += kq.w * w3.z; ap3 += kq.w * w3.w;
            }
            size_t orow = (size_t)((c << 4) + m3) * HID + e3;
            *(float4*)&obase[orow] = make_float4(ap0, ap1, ap2, ap3);
        }
    }
}

// ---------------------------------------------------------------------------
// LayerNorm (in place on g_o)
// ---------------------------------------------------------------------------
__global__ __launch_bounds__(256)
void ln_kernel(float* __restrict__ o,
               const float* __restrict__ g,
               const float* __restrict__ beta)
{
    __shared__ float s1[8], s2[8];
    const int row = blockIdx.x;
    const int t   = threadIdx.x;
    float* p = o + (size_t)row * HID;

    float4 v0 = *(const float4*)(p + t * 8);
    float4 v1 = *(const float4*)(p + t * 8 + 4);
    float s  = v0.x + v0.y + v0.z + v0.w + v1.x + v1.y + v1.z + v1.w;
    float ss = v0.x*v0.x + v0.y*v0.y + v0.z*v0.z + v0.w*v0.w
             + v1.x*v1.x + v1.y*v1.y + v1.z*v1.z + v1.w*v1.w;
#pragma unroll
    for (int off = 16; off > 0; off >>= 1) {
        s  += __shfl_xor_sync(0xffffffffu, s,  off);
        ss += __shfl_xor_sync(0xffffffffu, ss, off);
    }
    const int w = t >> 5;
    if ((t & 31) == 0) { s1[w] = s; s2[w] = ss; }
    __syncthreads();
    float tot = 0.f, tot2 = 0.f;
#pragma unroll
    for (int i = 0; i < 8; ++i) { tot += s1[i]; tot2 += s2[i]; }
    const float mu  = tot * (1.0f / HID);
    const float var = tot2 * (1.0f / HID) - mu * mu;
    const float inv = rsqrtf(var + 1e-5f);

    float4 g0 = *(const float4*)(g + t * 8);
    float4 g1 = *(const float4*)(g + t * 8 + 4);
    float4 b0 = *(const float4*)(beta + t * 8);
    float4 b1 = *(const float4*)(beta + t * 8 + 4);
    v0.x = (v0.x - mu) * inv * g0.x + b0.x;
    v0.y = (v0.y - mu) * inv * g0.y + b0.y;
    v0.z = (v0.z - mu) * inv * g0.z + b0.z;
    v0.w = (v0.w - mu) * inv * g0.w + b0.w;
    v1.x = (v1.x - mu) * inv * g1.x + b1.x;
    v1.y = (v1.y - mu) * inv * g1.y + b1.y;
    v1.z = (v1.z - mu) * inv * g1.z + b1.z;
    v1.w = (v1.w - mu) * inv * g1.w + b1.w;
    *(float4*)(p + t * 8)     = v0;
    *(float4*)(p + t * 8 + 4) = v1;
}

// ---------------------------------------------------------------------------
// launch
// ---------------------------------------------------------------------------
extern "C" void kernel_launch(void* const* d_in, const int* in_sizes, int n_in,
                              void* d_out, int out_size)
{
    const float* x   = (const float*)d_in[0];
    const float* Wk  = (const float*)d_in[1];
    const float* Wv  = (const float*)d_in[2];
    const float* Wo  = (const float*)d_in[3];
    const float* lng = (const float*)d_in[4];
    const float* lnb = (const float*)d_in[5];
    const float* W0  = (const float*)d_in[6];
    float* out = (float*)d_out;

    float *gk, *gv, *go;
    __nv_bfloat16 *ahi, *alo, *whi, *wlo;
    cudaGetSymbolAddress((void**)&gk, g_k);
    cudaGetSymbolAddress((void**)&gv, g_v);
    cudaGetSymbolAddress((void**)&go, g_o);
    cudaGetSymbolAddress((void**)&ahi, g_ahi);
    cudaGetSymbolAddress((void**)&alo, g_alo);
    cudaGetSymbolAddress((void**)&whi, g_whi);
    cudaGetSymbolAddress((void**)&wlo, g_wlo);

    cudaFuncSetAttribute(ttt_scan_kernel,
                         cudaFuncAttributeMaxDynamicSharedMemorySize, SCAN_SMEM);
    cudaFuncSetAttribute(gemm_mma_kernel,
                         cudaFuncAttributeMaxDynamicSharedMemorySize, GEMM_SMEM);

    const int nx4 = (Mrows * HID) / 4;
    const int nw4 = (HID * HID) / 4;
    dim3 gg(Ndim / 128, Mrows / 128);    // (16, 64)

    // split x
    cvt_hilo_kernel<<<(nx4 + 255) / 256, 256>>>(x, ahi, alo, nx4);

    // k = x @ Wk^T
    cvt_hilo_kernel<<<(nw4 + 255) / 256, 256>>>(Wk, whi, wlo, nw4);
    gemm_mma_kernel<<<gg, 256, GEMM_SMEM>>>(ahi, alo, whi, wlo, gk, nullptr);

    // v = x @ Wv^T
    cvt_hilo_kernel<<<(nw4 + 255) / 256, 256>>>(Wv, whi, wlo, nw4);
    gemm_mma_kernel<<<gg, 256, GEMM_SMEM>>>(ahi, alo, whi, wlo, gv, nullptr);

    // RoPE on k
    {
        const int total = Bsz * Ssz * HEADS * (HDIM / 2);
        rope_kernel<<<(total + 255) / 256, 256>>>(gk);
    }

    // TTT scan -> o
    ttt_scan_kernel<<<Bsz * HEADS, 512, SCAN_SMEM>>>(gk, gv, W0, go);

    // LayerNorm in place, then split to bf16
    ln_kernel<<<Mrows, 256>>>(go, lng, lnb);
    cvt_hilo_kernel<<<(nx4 + 255) / 256, 256>>>(go, ahi, alo, nx4);

    // out = x + o_ln @ Wo^T
    cvt_hilo_kernel<<<(nw4 + 255) / 256, 256>>>(Wo, whi, wlo, nw4);
    gemm_mma_kernel<<<gg, 256, GEMM_SMEM>>>(ahi, alo, whi, wlo, out, x);
}

// round 4
// speedup vs baseline: 3.8872x; 1.9273x over previous
#include <cuda_runtime.h>
#include <cuda_bf16.h>
#include <cstdint>

// Problem constants
#define Bsz   4
#define Ssz   2048
#define HID   2048
#define HEADS 16
#define HDIM  128
#define MBsz  16
#define NCH   128
#define Mrows (Bsz*Ssz)    // 8192
#define Kdim  2048
#define Ndim  2048

// Scratch (device globals: allocation-free rule)
__device__ float g_k[(size_t)Mrows * HID];
__device__ float g_v[(size_t)Mrows * HID];
__device__ float g_o[(size_t)Mrows * HID];
__device__ __nv_bfloat16 g_ahi[(size_t)Mrows * HID];
__device__ __nv_bfloat16 g_alo[(size_t)Mrows * HID];
__device__ __nv_bfloat16 g_whi[(size_t)HID * HID];
__device__ __nv_bfloat16 g_wlo[(size_t)HID * HID];

// ---------------------------------------------------------------------------
// helpers (baseline PTX only: cp.async / ldmatrix / mma.sync — sm_80 features)
// ---------------------------------------------------------------------------
__device__ __forceinline__ uint32_t smem_u32(const void* p) {
    uint32_t a;
    asm("{ .reg .u64 t; cvta.to.shared.u64 t, %1; cvt.u32.u64 %0, t; }"
        : "=r"(a) : "l"(p));
    return a;
}

#define SWZ(x) ((x) ^ (((x) >> 3) & 0x70))

__device__ __forceinline__ void cp16(uint32_t dst, const void* src) {
    asm volatile("cp.async.cg.shared.global [%0], [%1], 16;\n"
                 :: "r"(dst), "l"(src) : "memory");
}
__device__ __forceinline__ void cp_commit() {
    asm volatile("cp.async.commit_group;\n" ::: "memory");
}
template <int N> __device__ __forceinline__ void cp_wait() {
    asm volatile("cp.async.wait_group %0;\n" :: "n"(N) : "memory");
}

__device__ __forceinline__ void ldsm4(uint32_t r[4], uint32_t a) {
    asm volatile("ldmatrix.sync.aligned.m8n8.x4.shared.b16 {%0,%1,%2,%3}, [%4];"
                 : "=r"(r[0]), "=r"(r[1]), "=r"(r[2]), "=r"(r[3]) : "r"(a));
}

__device__ __forceinline__ void mma16816(float c[4], const uint32_t a[4],
                                         const uint32_t b0, const uint32_t b1) {
    asm volatile(
        "mma.sync.aligned.m16n8k16.row.col.f32.bf16.bf16.f32 "
        "{%0,%1,%2,%3}, {%4,%5,%6,%7}, {%8,%9}, {%0,%1,%2,%3};"
        : "+f"(c[0]), "+f"(c[1]), "+f"(c[2]), "+f"(c[3])
        : "r"(a[0]), "r"(a[1]), "r"(a[2]), "r"(a[3]), "r"(b0), "r"(b1));
}

__device__ __forceinline__ void bsplit(float x, uint16_t& h, uint16_t& l) {
    __nv_bfloat16 hb = __float2bfloat16_rn(x);
    __nv_bfloat16 lb = __float2bfloat16_rn(x - __bfloat162float(hb));
    h = *(uint16_t*)&hb;
    l = *(uint16_t*)&lb;
}

// ---------------------------------------------------------------------------
// fp32 -> bf16 hi/lo split converter
// ---------------------------------------------------------------------------
__global__ __launch_bounds__(256)
void cvt_hilo_kernel(const float* __restrict__ s,
                     __nv_bfloat16* __restrict__ hi,
                     __nv_bfloat16* __restrict__ lo, int n4)
{
    int i = blockIdx.x * blockDim.x + threadIdx.x;
    if (i >= n4) return;
    float4 v = ((const float4*)s)[i];
    __nv_bfloat16 h0 = __float2bfloat16_rn(v.x);
    __nv_bfloat16 h1 = __float2bfloat16_rn(v.y);
    __nv_bfloat16 h2 = __float2bfloat16_rn(v.z);
    __nv_bfloat16 h3 = __float2bfloat16_rn(v.w);
    __nv_bfloat16 l0 = __float2bfloat16_rn(v.x - __bfloat162float(h0));
    __nv_bfloat16 l1 = __float2bfloat16_rn(v.y - __bfloat162float(h1));
    __nv_bfloat16 l2 = __float2bfloat16_rn(v.z - __bfloat162float(h2));
    __nv_bfloat16 l3 = __float2bfloat16_rn(v.w - __bfloat162float(h3));
    __nv_bfloat162* H = (__nv_bfloat162*)hi;
    __nv_bfloat162* L = (__nv_bfloat162*)lo;
    H[2 * i]     = __halves2bfloat162(h0, h1);
    H[2 * i + 1] = __halves2bfloat162(h2, h3);
    L[2 * i]     = __halves2bfloat162(l0, l1);
    L[2 * i + 1] = __halves2bfloat162(l2, l3);
}

// ---------------------------------------------------------------------------
// mma.sync bf16 hi/lo GEMM: C[M,N] = A[M,K] @ B[N,K]^T (+ optional residual)
// (unchanged from R3 — near its throughput floor)
// ---------------------------------------------------------------------------
#define GS      3
#define TILE_B  16384
#define STAGE_B (4 * TILE_B)
#define GEMM_SMEM (1024 + GS * STAGE_B)
#define KTILES  (Kdim / 64)

__global__ __launch_bounds__(256, 1)
void gemm_mma_kernel(const __nv_bfloat16* __restrict__ Ahi,
                     const __nv_bfloat16* __restrict__ Alo,
                     const __nv_bfloat16* __restrict__ Bhi,
                     const __nv_bfloat16* __restrict__ Blo,
                     float* __restrict__ C,
                     const float* __restrict__ Res)
{
    extern __shared__ uint8_t smraw[];
    const uint32_t s0 = (smem_u32(smraw) + 1023u) & ~1023u;

    const int tid  = threadIdx.x;
    const int wid  = tid >> 5;
    const int lane = tid & 31;
    const int wm   = wid & 1;
    const int wn   = wid >> 1;
    const int m0 = blockIdx.y * 128;
    const int n0 = blockIdx.x * 128;

    uint32_t aBase[4];
    {
        int amat = lane >> 3, al = lane & 7;
        int rofs = ((amat & 1) << 3) + al;
        uint32_t akb = (uint32_t)((amat >> 1) << 4);
#pragma unroll
        for (int mf = 0; mf < 4; ++mf) {
            uint32_t r = (uint32_t)(wm * 64 + mf * 16 + rofs) * 128u;
            aBase[mf] = SWZ(r) ^ akb;
        }
    }
    uint32_t bBase[2];
    {
        int bmat = lane >> 3, bl = lane & 7;
        int rofs = ((bmat >> 1) << 3) + bl;
        uint32_t bkb = (uint32_t)((bmat & 1) << 4);
#pragma unroll
        for (int nfp = 0; nfp < 2; ++nfp) {
            uint32_t r = (uint32_t)(wn * 32 + nfp * 16 + rofs) * 128u;
            bBase[nfp] = SWZ(r) ^ bkb;
        }
    }

    auto load_stage = [&](int kt) {
        uint32_t sb = s0 + (uint32_t)(kt % GS) * STAGE_B;
        const size_t kof = (size_t)kt * 64;
#pragma unroll
        for (int j = 0; j < 4; ++j) {
            int q = j * 256 + tid;
            int row = q >> 3, ch = q & 7;
            uint32_t so = SWZ((uint32_t)(row * 128 + ch * 16));
            size_t ga = (size_t)(m0 + row) * Kdim + kof + (size_t)ch * 8;
            size_t gb = (size_t)(n0 + row) * Kdim + kof + (size_t)ch * 8;
            cp16(sb + so,              Ahi + ga);
            cp16(sb + TILE_B + so,     Alo + ga);
            cp16(sb + 2 * TILE_B + so, Bhi + gb);
            cp16(sb + 3 * TILE_B + so, Blo + gb);
        }
        cp_commit();
    };

    float acc[4][4][4];
#pragma unroll
    for (int i = 0; i < 4; ++i)
#pragma unroll
        for (int j = 0; j < 4; ++j)
#pragma unroll
            for (int r = 0; r < 4; ++r) acc[i][j][r] = 0.f;

    load_stage(0);
    load_stage(1);

    for (int it = 0; it < KTILES; ++it) {
        cp_wait<1>();
        __syncthreads();
        if (it + 2 < KTILES) load_stage(it + 2);

        const uint32_t sb = s0 + (uint32_t)(it % GS) * STAGE_B;
#pragma unroll
        for (int kk = 0; kk < 4; ++kk) {
            const uint32_t kx = (uint32_t)(kk * 32);
            uint32_t ah[4][4], al[4][4];
#pragma unroll
            for (int mf = 0; mf < 4; ++mf) {
                ldsm4(ah[mf], sb + (aBase[mf] ^ kx));
                ldsm4(al[mf], sb + TILE_B + (aBase[mf] ^ kx));
            }
            uint32_t bh[4][2], bl[4][2];
#pragma unroll
            for (int nfp = 0; nfp < 2; ++nfp) {
                uint32_t t[4];
                ldsm4(t, sb + 2 * TILE_B + (bBase[nfp] ^ kx));
                bh[2 * nfp][0] = t[0]; bh[2 * nfp][1] = t[1];
                bh[2 * nfp + 1][0] = t[2]; bh[2 * nfp + 1][1] = t[3];
                ldsm4(t, sb + 3 * TILE_B + (bBase[nfp] ^ kx));
                bl[2 * nfp][0] = t[0]; bl[2 * nfp][1] = t[1];
                bl[2 * nfp + 1][0] = t[2]; bl[2 * nfp + 1][1] = t[3];
            }
#pragma unroll
            for (int mf = 0; mf < 4; ++mf)
#pragma unroll
                for (int nf = 0; nf < 4; ++nf) {
                    mma16816(acc[mf][nf], ah[mf], bh[nf][0], bh[nf][1]);
                    mma16816(acc[mf][nf], ah[mf], bl[nf][0], bl[nf][1]);
                    mma16816(acc[mf][nf], al[mf], bh[nf][0], bh[nf][1]);
                }
        }
    }

    const int cm = (lane >> 2);
    const int cn = (lane & 3) * 2;
#pragma unroll
    for (int mf = 0; mf < 4; ++mf) {
        const int row = m0 + wm * 64 + mf * 16 + cm;
#pragma unroll
        for (int nf = 0; nf < 4; ++nf) {
            const int col = n0 + wn * 32 + nf * 8 + cn;
            float2 v0 = make_float2(acc[mf][nf][0], acc[mf][nf][1]);
            float2 v1 = make_float2(acc[mf][nf][2], acc[mf][nf][3]);
            if (Res) {
                float2 r0 = *(const float2*)(Res + (size_t)row * Ndim + col);
                float2 r1 = *(const float2*)(Res + (size_t)(row + 8) * Ndim + col);
                v0.x += r0.x; v0.y += r0.y;
                v1.x += r1.x; v1.y += r1.y;
            }
            *(float2*)(C + (size_t)row * Ndim + col)       = v0;
            *(float2*)(C + (size_t)(row + 8) * Ndim + col) = v1;
        }
    }
}

// ---------------------------------------------------------------------------
// RoPE on g_k
// ---------------------------------------------------------------------------
__global__ void rope_kernel(float* __restrict__ k)
{
    const int gid = blockIdx.x * blockDim.x + threadIdx.x;
    const int total = Bsz * Ssz * HEADS * (HDIM / 2);
    if (gid >= total) return;
    const int i   = gid & 63;
    const int h   = (gid >> 6) & (HEADS - 1);
    const int row = gid >> 10;
    const int s   = row & (Ssz - 1);

    const float c = 0.20762050593046013f;   // log2(10000)/64
    const float inv = exp2f(-c * (float)i);
    const float ang = (float)s * inv;
    float sn = sinf(ang), cs = cosf(ang);

    float* p = k + (size_t)row * HID + h * HDIM;
    const float k1 = p[i];
    const float k2 = p[i + 64];
    p[i]      = k1 * cs - k2 * sn;
    p[i + 64] = k2 * cs + k1 * sn;
}

// ---------------------------------------------------------------------------
// Tensor-core TTT scan. Grid (64 bh, 2 e-halves), 128 threads (4 warps).
// W[128d x 64e] lives in fp32 mma accumulator fragments; per chunk:
//   E' = (V - pred)/1024  -> ET[e][m] bf16 hi/lo
//   W += K^T @ E'         (mma, 3 hi/lo products, accum straight into W)
//   dump W -> WT[e][d] bf16 hi/lo
//   out_c = K_c @ W ; pred_{c+1} = K_{c+1} @ W   (fused, shared B loads)
// ---------------------------------------------------------------------------
#define OFF_RAWK   0            // [2][16][128] f32 = 16384
#define OFF_RAWV   16384        // [2][16][64]  f32 = 8192
#define OFF_KHI    24576        // [2 buf][2 half][16*128B] = 8192
#define OFF_KLO    32768        // 8192
#define OFF_KTHI   40960        // [128][48B] = 6144
#define OFF_KTLO   47104        // 6144
#define OFF_ETHI   53248        // [64][48B] = 3072
#define OFF_ETLO   56320        // 3072
#define OFF_WTHI   59392        // [2 half][64*128B] = 16384
#define OFF_WTLO   75776        // 16384
#define SCAN2_SMEM 92160

__global__ __launch_bounds__(128, 1)
void ttt_scan_mma(const float* __restrict__ gk,
                  const float* __restrict__ gv,
                  const float* __restrict__ W0,
                  float*       __restrict__ go)
{
    extern __shared__ __align__(16) char sm[];
    const uint32_t sb = smem_u32(sm);

    const int tid  = threadIdx.x;
    const int wid  = tid >> 5;
    const int lane = tid & 31;
    const int bh = blockIdx.x;           // 0..63
    const int eh = blockIdx.y;           // 0..1
    const int b  = bh >> 4, h = bh & 15;
    const int e0 = eh * 64;

    // ldmatrix address components (R3-verified patterns)
    const int mat = lane >> 3, ml = lane & 7;
    const int arow = ((mat & 1) << 3) + ml;          // A-operand row pattern
    const uint32_t akb = (uint32_t)((mat >> 1) << 4);
    const int brow = ((mat >> 1) << 3) + ml;         // B-operand row pattern
    const uint32_t bkb = (uint32_t)((mat & 1) << 4);

    const uint32_t aBaseK = SWZ((uint32_t)(arow * 128)) ^ akb;              // K tiles
    const uint32_t bBaseW = SWZ((uint32_t)((16 * wid + brow) * 128)) ^ bkb; // WT tiles

    const int cr = lane >> 2;            // accumulator row 0..7
    const int cc = (lane & 3) * 2;       // accumulator col base

    // ---- W fragments: warp wid owns d in [32w, 32w+32), e in [0,64) local
    float W[2][8][4];
    {
        const float* W0p = W0 + (size_t)bh * (HDIM * HDIM);
#pragma unroll
        for (int t2 = 0; t2 < 2; ++t2) {
            int dt = 32 * wid + 16 * t2;
#pragma unroll
            for (int j = 0; j < 8; ++j) {
                int e = e0 + 8 * j + cc;
                W[t2][j][0] = W0p[(size_t)(dt + cr) * 128 + e];
                W[t2][j][1] = W0p[(size_t)(dt + cr) * 128 + e + 1];
                W[t2][j][2] = W0p[(size_t)(dt + cr + 8) * 128 + e];
                W[t2][j][3] = W0p[(size_t)(dt + cr + 8) * 128 + e + 1];
            }
        }
    }

    const float* kbase = gk + (size_t)b * Ssz * HID + h * HDIM;
    const float* vbase = gv + (size_t)b * Ssz * HID + h * HDIM + e0;
    float*       obase = go + (size_t)b * Ssz * HID + h * HDIM + e0;

    // ---- lambdas -----------------------------------------------------------
    auto dumpW = [&]() {
#pragma unroll
        for (int t2 = 0; t2 < 2; ++t2) {
            int dt = 32 * wid + 16 * t2;
#pragma unroll
            for (int j = 0; j < 8; ++j) {
                int e = 8 * j + cc;
#pragma unroll
                for (int q = 0; q < 4; ++q) {
                    int d  = dt + cr + ((q >> 1) << 3);
                    int ee = e + (q & 1);
                    uint16_t hh, ll;
                    bsplit(W[t2][j][q], hh, ll);
                    uint32_t half = (uint32_t)(d >> 6);
                    uint32_t a = SWZ((uint32_t)(ee * 128 + (d & 63) * 2));
                    *(uint16_t*)(sm + OFF_WTHI + half * 8192 + a) = hh;
                    *(uint16_t*)(sm + OFF_WTLO + half * 8192 + a) = ll;
                }
            }
        }
    };

    auto loadKV = [&](int c) {
        int buf = c & 1;
        const float* ks = kbase + (size_t)(c * 16) * HID;
        const float* vs = vbase + (size_t)(c * 16) * HID;
#pragma unroll
        for (int j = 0; j < 4; ++j) {
            int q = j * 128 + tid;
            int row = q >> 5, ch = q & 31;
            cp16(sb + OFF_RAWK + buf * 8192 + (uint32_t)(row * 512 + ch * 16),
                 ks + (size_t)row * HID + ch * 4);
        }
#pragma unroll
        for (int j = 0; j < 2; ++j) {
            int q = j * 128 + tid;
            int row = q >> 4, ch = q & 15;
            cp16(sb + OFF_RAWV + buf * 4096 + (uint32_t)(row * 256 + ch * 16),
                 vs + (size_t)row * HID + ch * 4);
        }
        cp_commit();
    };

    auto convK = [&](int c) {     // raw K -> Khi/Klo ldsm tiles
        int buf = c & 1;
        const float* rk = (const float*)(sm + OFF_RAWK + buf * 8192);
        int m = tid >> 3, c16 = (tid & 7) * 16;
        __align__(16) uint16_t hb[16], lb[16];
#pragma unroll
        for (int i = 0; i < 16; ++i) bsplit(rk[m * 128 + c16 + i], hb[i], lb[i]);
        uint32_t half = (uint32_t)(c16 >= 64);
        uint32_t ccl  = (uint32_t)((c16 & 63) * 2);
        uint32_t a0 = SWZ((uint32_t)(m * 128) + ccl);
        uint32_t a1 = SWZ((uint32_t)(m * 128) + ccl + 16);
        uint32_t kb = (uint32_t)(OFF_KHI + buf * 4096 + half * 2048);
        *(uint4*)(sm + kb + a0) = *(uint4*)&hb[0];
        *(uint4*)(sm + kb + a1) = *(uint4*)&hb[8];
        kb = (uint32_t)(OFF_KLO + buf * 4096 + half * 2048);
        *(uint4*)(sm + kb + a0) = *(uint4*)&lb[0];
        *(uint4*)(sm + kb + a1) = *(uint4*)&lb[8];
    };

    auto convKT = [&](int c) {    // raw K -> KT[d][m] hi/lo (48B stride)
        int buf = c & 1;
        const float* rk = (const float*)(sm + OFF_RAWK + buf * 8192);
        int d = tid;
        __align__(16) uint16_t th[16], tl[16];
#pragma unroll
        for (int m = 0; m < 16; ++m) bsplit(rk[m * 128 + d], th[m], tl[m]);
        *(uint4*)(sm + OFF_KTHI + d * 48)      = *(uint4*)&th[0];
        *(uint4*)(sm + OFF_KTHI + d * 48 + 16) = *(uint4*)&th[8];
        *(uint4*)(sm + OFF_KTLO + d * 48)      = *(uint4*)&tl[0];
        *(uint4*)(sm + OFF_KTLO + d * 48 + 16) = *(uint4*)&tl[8];
    };

    float P[2][4];    // pred fragments (warp's e-slice [16w,16w+16))

    // pred phase for one K buffer into acc[2][4] (no out)
    auto predOnly = [&](int buf, float acc[2][4]) {
#pragma unroll
        for (int f = 0; f < 2; ++f)
#pragma unroll
            for (int q = 0; q < 4; ++q) acc[f][q] = 0.f;
#pragma unroll
        for (int kk = 0; kk < 8; ++kk) {
            uint32_t half = (uint32_t)(kk >> 2);
            uint32_t kx   = (uint32_t)((kk & 3) * 32);
            uint32_t ah[4], al[4], t[4], bh[2][2], bl[2][2];
            ldsm4(ah, sb + OFF_KHI + buf * 4096 + half * 2048 + (aBaseK ^ kx));
            ldsm4(al, sb + OFF_KLO + buf * 4096 + half * 2048 + (aBaseK ^ kx));
            ldsm4(t, sb + OFF_WTHI + half * 8192 + (bBaseW ^ kx));
            bh[0][0] = t[0]; bh[0][1] = t[1]; bh[1][0] = t[2]; bh[1][1] = t[3];
            ldsm4(t, sb + OFF_WTLO + half * 8192 + (bBaseW ^ kx));
            bl[0][0] = t[0]; bl[0][1] = t[1]; bl[1][0] = t[2]; bl[1][1] = t[3];
#pragma unroll
            for (int f = 0; f < 2; ++f) {
                mma16816(acc[f], ah, bh[f][0], bh[f][1]);
                mma16816(acc[f], ah, bl[f][0], bl[f][1]);
                mma16816(acc[f], al, bh[f][0], bh[f][1]);
            }
        }
    };

    // ---- prologue ----------------------------------------------------------
    dumpW();
    loadKV(0);
    cp_wait<0>();
    __syncthreads();
    convK(0);
    __syncthreads();
    predOnly(0, P);

    // ---- main loop ---------------------------------------------------------
    for (int c = 0; c < NCH; ++c) {
        const int buf = c & 1;
        const bool hasNext = (c + 1 < NCH);
        if (hasNext) loadKV(c + 1);

        convKT(c);

        // E' = (V - pred) / 1024, store ET[e][m] hi/lo
        {
            const float* rv = (const float*)(sm + OFF_RAWV + buf * 4096);
#pragma unroll
            for (int f = 0; f < 2; ++f)
#pragma unroll
                for (int q = 0; q < 4; ++q) {
                    int e = 16 * wid + 8 * f + cc + (q & 1);
                    int m = cr + ((q >> 1) << 3);
                    float ep = (rv[m * 64 + e] - P[f][q]) * 0.0009765625f;
                    uint16_t hh, ll;
                    bsplit(ep, hh, ll);
                    *(uint16_t*)(sm + OFF_ETHI + e * 48 + m * 2) = hh;
                    *(uint16_t*)(sm + OFF_ETLO + e * 48 + m * 2) = ll;
                }
        }
        __syncthreads();   // (A) ET, KT visible; prior WT readers done

        // W += K^T @ E'
        {
            uint32_t aH[2][4], aL[2][4];
#pragma unroll
            for (int t2 = 0; t2 < 2; ++t2) {
                uint32_t ra = (uint32_t)((32 * wid + 16 * t2 + arow) * 48) + akb;
                ldsm4(aH[t2], sb + OFF_KTHI + ra);
                ldsm4(aL[t2], sb + OFF_KTLO + ra);
            }
#pragma unroll
            for (int p = 0; p < 4; ++p) {
                uint32_t rb = (uint32_t)((16 * p + brow) * 48) + bkb;
                uint32_t th[4], tl[4];
                ldsm4(th, sb + OFF_ETHI + rb);
                ldsm4(tl, sb + OFF_ETLO + rb);
#pragma unroll
                for (int t2 = 0; t2 < 2; ++t2) {
                    mma16816(W[t2][2 * p],     aH[t2], th[0], th[1]);
                    mma16816(W[t2][2 * p],     aH[t2], tl[0], tl[1]);
                    mma16816(W[t2][2 * p],     aL[t2], th[0], th[1]);
                    mma16816(W[t2][2 * p + 1], aH[t2], th[2], th[3]);
                    mma16816(W[t2][2 * p + 1], aH[t2], tl[2], tl[3]);
                    mma16816(W[t2][2 * p + 1], aL[t2], th[2], th[3]);
                }
            }
        }

        dumpW();

        if (hasNext) cp_wait<0>();
        __syncthreads();   // (B) WT + raw[c+1] visible
        if (hasNext) convK(c + 1);
        __syncthreads();   // (C) Khi[c+1] visible

        // fused: out_c = K_c @ W_new (+ pred_{c+1} = K_{c+1} @ W_new)
        {
            float O[2][4];
#pragma unroll
            for (int f = 0; f < 2; ++f)
#pragma unroll
                for (int q = 0; q < 4; ++q) { O[f][q] = 0.f; P[f][q] = 0.f; }
            const int bufn = (c + 1) & 1;
#pragma unroll
            for (int kk = 0; kk < 8; ++kk) {
                uint32_t half = (uint32_t)(kk >> 2);
                uint32_t kx   = (uint32_t)((kk & 3) * 32);
                uint32_t t[4], bh[2][2], bl[2][2];
                ldsm4(t, sb + OFF_WTHI + half * 8192 + (bBaseW ^ kx));
                bh[0][0] = t[0]; bh[0][1] = t[1]; bh[1][0] = t[2]; bh[1][1] = t[3];
                ldsm4(t, sb + OFF_WTLO + half * 8192 + (bBaseW ^ kx));
                bl[0][0] = t[0]; bl[0][1] = t[1]; bl[1][0] = t[2]; bl[1][1] = t[3];

                uint32_t ah[4], al[4];
                ldsm4(ah, sb + OFF_KHI + buf * 4096 + half * 2048 + (aBaseK ^ kx));
                ldsm4(al, sb + OFF_KLO + buf * 4096 + half * 2048 + (aBaseK ^ kx));
#pragma unroll
                for (int f = 0; f < 2; ++f) {
                    mma16816(O[f], ah, bh[f][0], bh[f][1]);
                    mma16816(O[f], ah, bl[f][0], bl[f][1]);
                    mma16816(O[f], al, bh[f][0], bh[f][1]);
                }
                if (hasNext) {
                    uint32_t nh[4], nl[4];
                    ldsm4(nh, sb + OFF_KHI + bufn * 4096 + half * 2048 + (aBaseK ^ kx));
                    ldsm4(nl, sb + OFF_KLO + bufn * 4096 + half * 2048 + (aBaseK ^ kx));
#pragma unroll
                    for (int f = 0; f < 2; ++f) {
                        mma16816(P[f], nh, bh[f][0], bh[f][1]);
                        mma16816(P[f], nh, bl[f][0], bl[f][1]);
                        mma16816(P[f], nl, bh[f][0], bh[f][1]);
                    }
                }
            }
            // write out_c
#pragma unroll
            for (int f = 0; f < 2; ++f) {
                int e = 16 * wid + 8 * f + cc;
                size_t r0 = (size_t)(c * 16 + cr) * HID + e;
                size_t r1 = (size_t)(c * 16 + cr + 8) * HID + e;
                *(float2*)(obase + r0) = make_float2(O[f][0], O[f][1]);
                *(float2*)(obase + r1) = make_float2(O[f][2], O[f][3]);
            }
        }
    }
}

// ---------------------------------------------------------------------------
// LayerNorm (in place on g_o)
// ---------------------------------------------------------------------------
__global__ __launch_bounds__(256)
void ln_kernel(float* __restrict__ o,
               const float* __restrict__ g,
               const float* __restrict__ beta)
{
    __shared__ float s1[8], s2[8];
    const int row = blockIdx.x;
    const int t   = threadIdx.x;
    float* p = o + (size_t)row * HID;

    float4 v0 = *(const float4*)(p + t * 8);
    float4 v1 = *(const float4*)(p + t * 8 + 4);
    float s  = v0.x + v0.y + v0.z + v0.w + v1.x + v1.y + v1.z + v1.w;
    float ss = v0.x*v0.x + v0.y*v0.y + v0.z*v0.z + v0.w*v0.w
             + v1.x*v1.x + v1.y*v1.y + v1.z*v1.z + v1.w*v1.w;
#pragma unroll
    for (int off = 16; off > 0; off >>= 1) {
        s  += __shfl_xor_sync(0xffffffffu, s,  off);
        ss += __shfl_xor_sync(0xffffffffu, ss, off);
    }
    const int w = t >> 5;
    if ((t & 31) == 0) { s1[w] = s; s2[w] = ss; }
    __syncthreads();
    float tot = 0.f, tot2 = 0.f;
#pragma unroll
    for (int i = 0; i < 8; ++i) { tot += s1[i]; tot2 += s2[i]; }
    const float mu  = tot * (1.0f / HID);
    const float var = tot2 * (1.0f / HID) - mu * mu;
    const float inv = rsqrtf(var + 1e-5f);

    float4 g0 = *(const float4*)(g + t * 8);
    float4 g1 = *(const float4*)(g + t * 8 + 4);
    float4 b0 = *(const float4*)(beta + t * 8);
    float4 b1 = *(const float4*)(beta + t * 8 + 4);
    v0.x = (v0.x - mu) * inv * g0.x + b0.x;
    v0.y = (v0.y - mu) * inv * g0.y + b0.y;
    v0.z = (v0.z - mu) * inv * g0.z + b0.z;
    v0.w = (v0.w - mu) * inv * g0.w + b0.w;
    v1.x = (v1.x - mu) * inv * g1.x + b1.x;
    v1.y = (v1.y - mu) * inv * g1.y + b1.y;
    v1.z = (v1.z - mu) * inv * g1.z + b1.z;
    v1.w = (v1.w - mu) * inv * g1.w + b1.w;
    *(float4*)(p + t * 8)     = v0;
    *(float4*)(p + t * 8 + 4) = v1;
}

// ---------------------------------------------------------------------------
// launch
// ---------------------------------------------------------------------------
extern "C" void kernel_launch(void* const* d_in, const int* in_sizes, int n_in,
                              void* d_out, int out_size)
{
    const float* x   = (const float*)d_in[0];
    const float* Wk  = (const float*)d_in[1];
    const float* Wv  = (const float*)d_in[2];
    const float* Wo  = (const float*)d_in[3];
    const float* lng = (const float*)d_in[4];
    const float* lnb = (const float*)d_in[5];
    const float* W0  = (const float*)d_in[6];
    float* out = (float*)d_out;

    float *gk, *gv, *go;
    __nv_bfloat16 *ahi, *alo, *whi, *wlo;
    cudaGetSymbolAddress((void**)&gk, g_k);
    cudaGetSymbolAddress((void**)&gv, g_v);
    cudaGetSymbolAddress((void**)&go, g_o);
    cudaGetSymbolAddress((void**)&ahi, g_ahi);
    cudaGetSymbolAddress((void**)&alo, g_alo);
    cudaGetSymbolAddress((void**)&whi, g_whi);
    cudaGetSymbolAddress((void**)&wlo, g_wlo);

    cudaFuncSetAttribute(ttt_scan_mma,
                         cudaFuncAttributeMaxDynamicSharedMemorySize, SCAN2_SMEM);
    cudaFuncSetAttribute(gemm_mma_kernel,
                         cudaFuncAttributeMaxDynamicSharedMemorySize, GEMM_SMEM);

    const int nx4 = (Mrows * HID) / 4;
    const int nw4 = (HID * HID) / 4;
    dim3 gg(Ndim / 128, Mrows / 128);    // (16, 64)

    // split x
    cvt_hilo_kernel<<<(nx4 + 255) / 256, 256>>>(x, ahi, alo, nx4);

    // k = x @ Wk^T
    cvt_hilo_kernel<<<(nw4 + 255) / 256, 256>>>(Wk, whi, wlo, nw4);
    gemm_mma_kernel<<<gg, 256, GEMM_SMEM>>>(ahi, alo, whi, wlo, gk, nullptr);

    // v = x @ Wv^T
    cvt_hilo_kernel<<<(nw4 + 255) / 256, 256>>>(Wv, whi, wlo, nw4);
    gemm_mma_kernel<<<gg, 256, GEMM_SMEM>>>(ahi, alo, whi, wlo, gv, nullptr);

    // RoPE on k
    {
        const int total = Bsz * Ssz * HEADS * (HDIM / 2);
        rope_kernel<<<(total + 255) / 256, 256>>>(gk);
    }

    // TTT scan -> o  (tensor-core, e-split)
    {
        dim3 sg(Bsz * HEADS, 2);
        ttt_scan_mma<<<sg, 128, SCAN2_SMEM>>>(gk, gv, W0, go);
    }

    // LayerNorm in place, then split to bf16
    ln_kernel<<<Mrows, 256>>>(go, lng, lnb);
    cvt_hilo_kernel<<<(nx4 + 255) / 256, 256>>>(go, ahi, alo, nx4);

    // out = x + o_ln @ Wo^T
    cvt_hilo_kernel<<<(nw4 + 255) / 256, 256>>>(Wo, whi, wlo, nw4);
    gemm_mma_kernel<<<gg, 256, GEMM_SMEM>>>(ahi, alo, whi, wlo, out, x);
}